// round 14
// baseline (speedup 1.0000x reference)
#include <cuda_runtime.h>
#include <cstdint>

// out[c, i, j, k, l] = tb[c,0,i] * tb[c,1,j] * tb[c,2,k] * tb[c,3,l]
// tb = tensor + bias, shapes (C=2048, 4, 16). Output (C, 16,16,16,16) fp32.
//
// Pure store-bandwidth kernel: 512 MB out, ~1 MB in.
// R14 = R7 schedule (32768 CTAs, one 16KB i-slice each, smem-staged
// inputs, st.global.v8 egress) with 128-thread CTAs: 4 independent v8
// stores per thread, 4-warp barrier groups, 16 CTAs/SM (same 64 warps
// resident). Block-shape gradient pointed smaller (512 bad, 256 good);
// this tests the next point down.

static constexpr int LDIM = 16;
static constexpr int NFAC = 4;
static constexpr int THREADS = 128;

__device__ __forceinline__ void stg_v8(float* p,
                                       float a, float b, float c, float d,
                                       float e, float f, float g, float h)
{
    asm volatile(
        "st.global.v8.b32 [%0], {%1, %2, %3, %4, %5, %6, %7, %8};"
        :: "l"(p),
           "r"(__float_as_uint(a)), "r"(__float_as_uint(b)),
           "r"(__float_as_uint(c)), "r"(__float_as_uint(d)),
           "r"(__float_as_uint(e)), "r"(__float_as_uint(f)),
           "r"(__float_as_uint(g)), "r"(__float_as_uint(h))
        : "memory");
}

__global__ __launch_bounds__(THREADS, 16)
void tpe_kernel(const float* __restrict__ tensor,
                const float* __restrict__ bias,
                float* __restrict__ out)
{
    __shared__ float s[NFAC * LDIM];

    const int b = blockIdx.x;
    const int c = b >> 4;          // channel
    const int i = b & 15;          // i slice: this CTA writes out[c, i, :, :, :]
    const int t = threadIdx.x;

    if (t < NFAC * LDIM) {
        const int g = c * (NFAC * LDIM) + t;
        s[t] = tensor[g] + bias[g];
    }
    __syncthreads();

    // float8 index within the i-slice: r = t + 128*m, m in [0,4).
    //   lh = r & 1, k = (r>>1) & 15  (fixed per thread, from t);
    //   j = (r>>5) & 15 = ((t>>5) & 3) | (m << 2).
    const int lh   = t & 1;
    const int k    = (t >> 1) & 15;
    const int jlow = (t >> 5) & 3;

    const float p2 = s[2 * LDIM + k];
    float v3[8];
    #pragma unroll
    for (int m = 0; m < 8; ++m) v3[m] = s[3 * LDIM + lh * 8 + m];

    const float a0 = s[i] * p2;

    float* ob = out + (size_t)c * 65536 + (size_t)i * 4096 + (size_t)t * 8;

    #pragma unroll
    for (int m = 0; m < 4; ++m) {
        const float a = a0 * s[LDIM + jlow + (m << 2)];
        stg_v8(ob + (size_t)m * 1024,
               a * v3[0], a * v3[1], a * v3[2], a * v3[3],
               a * v3[4], a * v3[5], a * v3[6], a * v3[7]);
    }
}

extern "C" void kernel_launch(void* const* d_in, const int* in_sizes, int n_in,
                              void* d_out, int out_size)
{
    const float* tensor = (const float*)d_in[0];
    const float* bias   = (const float*)d_in[1];
    float* out          = (float*)d_out;

    const int C = in_sizes[0] / (NFAC * LDIM);   // 2048

    tpe_kernel<<<C * 16, THREADS>>>(tensor, bias, out);
}

// round 15
// speedup vs baseline: 1.0084x; 1.0084x over previous
#include <cuda_runtime.h>
#include <cstdint>

// out[c, i, j, k, l] = tb[c,0,i] * tb[c,1,j] * tb[c,2,k] * tb[c,3,l]
// tb = tensor + bias, shapes (C=2048, 4, 16). Output (C, 16,16,16,16) fp32.
//
// Pure store-bandwidth kernel: 512 MB out, ~1 MB in.
// R15 = R14 replication (32768 CTAs x 128 threads, one 16KB i-slice per
// CTA, smem-staged inputs, 4 independent st.global.v8 per thread) with the
// min-blocks clamp dropped (regs=32 fits 16 CTAs/SM naturally).
// R14 had the session-best ncu profile (73.5us, DRAM 82.1%) but a wall
// sample 0.7us above R7; this replication decides 128-vs-256 threads.
// Session is at the HBM write ceiling: ~7.3 TB/s effective store rate,
// 91% of spec, invariant across STG / bulk-store egress paths.

static constexpr int LDIM = 16;
static constexpr int NFAC = 4;
static constexpr int THREADS = 128;

__device__ __forceinline__ void stg_v8(float* p,
                                       float a, float b, float c, float d,
                                       float e, float f, float g, float h)
{
    asm volatile(
        "st.global.v8.b32 [%0], {%1, %2, %3, %4, %5, %6, %7, %8};"
        :: "l"(p),
           "r"(__float_as_uint(a)), "r"(__float_as_uint(b)),
           "r"(__float_as_uint(c)), "r"(__float_as_uint(d)),
           "r"(__float_as_uint(e)), "r"(__float_as_uint(f)),
           "r"(__float_as_uint(g)), "r"(__float_as_uint(h))
        : "memory");
}

__global__ __launch_bounds__(THREADS)
void tpe_kernel(const float* __restrict__ tensor,
                const float* __restrict__ bias,
                float* __restrict__ out)
{
    __shared__ float s[NFAC * LDIM];

    const int b = blockIdx.x;
    const int c = b >> 4;          // channel
    const int i = b & 15;          // i slice: this CTA writes out[c, i, :, :, :]
    const int t = threadIdx.x;

    if (t < NFAC * LDIM) {
        const int g = c * (NFAC * LDIM) + t;
        s[t] = tensor[g] + bias[g];
    }
    __syncthreads();

    // float8 index within the i-slice: r = t + 128*m, m in [0,4).
    //   lh = r & 1, k = (r>>1) & 15  (fixed per thread, from t);
    //   j = (r>>5) & 15 = ((t>>5) & 3) | (m << 2).
    const int lh   = t & 1;
    const int k    = (t >> 1) & 15;
    const int jlow = (t >> 5) & 3;

    const float p2 = s[2 * LDIM + k];
    float v3[8];
    #pragma unroll
    for (int m = 0; m < 8; ++m) v3[m] = s[3 * LDIM + lh * 8 + m];

    const float a0 = s[i] * p2;

    float* ob = out + (size_t)c * 65536 + (size_t)i * 4096 + (size_t)t * 8;

    #pragma unroll
    for (int m = 0; m < 4; ++m) {
        const float a = a0 * s[LDIM + jlow + (m << 2)];
        stg_v8(ob + (size_t)m * 1024,
               a * v3[0], a * v3[1], a * v3[2], a * v3[3],
               a * v3[4], a * v3[5], a * v3[6], a * v3[7]);
    }
}

extern "C" void kernel_launch(void* const* d_in, const int* in_sizes, int n_in,
                              void* d_out, int out_size)
{
    const float* tensor = (const float*)d_in[0];
    const float* bias   = (const float*)d_in[1];
    float* out          = (float*)d_out;

    const int C = in_sizes[0] / (NFAC * LDIM);   // 2048

    tpe_kernel<<<C * 16, THREADS>>>(tensor, bias, out);
}